// round 1
// baseline (speedup 1.0000x reference)
#include <cuda_runtime.h>
#include <math.h>

#define D_EMB   1024
#define N_HEADS 16
#define DK      64
#define BATCH   2
#define SEQ     2048
#define MROWS   (BATCH*SEQ)   // 4096

// Scratch (allocation-free rule: __device__ globals)
__device__ float g_q[MROWS * D_EMB];
__device__ float g_k[MROWS * D_EMB];
__device__ float g_v[MROWS * D_EMB];
__device__ float g_attn[MROWS * D_EMB];

// ---------------------------------------------------------------------------
// GEMM (NT + bias): C[m,n] = sum_k A[m,k] * W[n,k] + bias[n]
// A: [M, 1024] row-major, W: [1024, 1024] row-major (row n = output feature n)
// BM=BN=128, BK=16, 256 threads, 8x8 micro-tile per thread.
// M divisible by 128, N=1024 divisible by 128, K=1024 divisible by 16.
// ---------------------------------------------------------------------------
__global__ __launch_bounds__(256)
void gemm_nt_bias(const float* __restrict__ A,
                  const float* __restrict__ W,
                  const float* __restrict__ bias,
                  float* __restrict__ C)
{
    __shared__ float As[16][128];
    __shared__ float Ws[16][128];

    const int t  = threadIdx.x;
    const int tx = t & 15;        // n micro index
    const int ty = t >> 4;        // m micro index
    const int m0 = blockIdx.y * 128;
    const int n0 = blockIdx.x * 128;

    float acc[8][8];
#pragma unroll
    for (int i = 0; i < 8; ++i)
#pragma unroll
        for (int j = 0; j < 8; ++j) acc[i][j] = 0.f;

    for (int kt = 0; kt < D_EMB / 16; ++kt) {
        const int k0 = kt * 16;
        // Load tiles: 128x16 floats each = 512 float4, 2 per thread.
#pragma unroll
        for (int i = 0; i < 2; ++i) {
            int id  = t + i * 256;          // 0..511
            int row = id >> 2;              // 0..127
            int kq  = id & 3;               // float4 within the 16-wide k slab
            float4 va = *(const float4*)&A[(size_t)(m0 + row) * D_EMB + k0 + kq * 4];
            As[kq * 4 + 0][row] = va.x;
            As[kq * 4 + 1][row] = va.y;
            As[kq * 4 + 2][row] = va.z;
            As[kq * 4 + 3][row] = va.w;
            float4 vw = *(const float4*)&W[(size_t)(n0 + row) * D_EMB + k0 + kq * 4];
            Ws[kq * 4 + 0][row] = vw.x;
            Ws[kq * 4 + 1][row] = vw.y;
            Ws[kq * 4 + 2][row] = vw.z;
            Ws[kq * 4 + 3][row] = vw.w;
        }
        __syncthreads();

#pragma unroll
        for (int kk = 0; kk < 16; ++kk) {
            float a[8], b[8];
            *(float4*)&a[0] = *(const float4*)&As[kk][ty * 8];
            *(float4*)&a[4] = *(const float4*)&As[kk][ty * 8 + 4];
            *(float4*)&b[0] = *(const float4*)&Ws[kk][tx * 8];
            *(float4*)&b[4] = *(const float4*)&Ws[kk][tx * 8 + 4];
#pragma unroll
            for (int i = 0; i < 8; ++i)
#pragma unroll
                for (int j = 0; j < 8; ++j)
                    acc[i][j] = fmaf(a[i], b[j], acc[i][j]);
        }
        __syncthreads();
    }

#pragma unroll
    for (int i = 0; i < 8; ++i) {
        const int m = m0 + ty * 8 + i;
#pragma unroll
        for (int j = 0; j < 8; ++j) {
            const int n = n0 + tx * 8 + j;
            C[(size_t)m * D_EMB + n] = acc[i][j] + bias[n];
        }
    }
}

// ---------------------------------------------------------------------------
// FlashAttention-style kernel (fp32).
// Grid: (S/64, H, B). Block: 256 threads (16x16), 4x4 micro-tiles.
// Per block: 64 queries, stream over 32 key-tiles of 64.
// Shared (dynamic): Qs[64][65] d-major, Ks[64][65] d-major, Ps[64][65], Vs[64][64]
// ---------------------------------------------------------------------------
#define QP 65
#define ATTN_SMEM_BYTES ((3 * 64 * QP + 64 * 64) * 4)

__global__ __launch_bounds__(256)
void attn_kernel(float* __restrict__ out)
{
    extern __shared__ float sm[];
    float* Qs = sm;                    // [d][q] pitch QP
    float* Ks = Qs + 64 * QP;          // [d][k] pitch QP
    float* Ps = Ks + 64 * QP;          // [q][k] pitch QP
    float* Vs = Ps + 64 * QP;          // [k][d] pitch 64

    const int t  = threadIdx.x;
    const int tx = t & 15;             // key / dk micro index
    const int ty = t >> 4;             // query micro index
    const int q0 = blockIdx.x * 64;
    const int h  = blockIdx.y;
    const int b  = blockIdx.z;

    const float* qptr = g_q + ((size_t)(b * SEQ)) * D_EMB + h * DK;
    const float* kptr = g_k + ((size_t)(b * SEQ)) * D_EMB + h * DK;
    const float* vptr = g_v + ((size_t)(b * SEQ)) * D_EMB + h * DK;

    // Load Q tile (scaled by 1/sqrt(dk)), d-major into smem.
    for (int idx = t; idx < 64 * 64; idx += 256) {
        int q = idx >> 6, d = idx & 63;
        Qs[d * QP + q] = qptr[(size_t)(q0 + q) * D_EMB + d] * 0.125f;
    }

    float o[4][4];
    float mrow[4], lrow[4];
#pragma unroll
    for (int i = 0; i < 4; ++i) {
        mrow[i] = -INFINITY; lrow[i] = 0.f;
#pragma unroll
        for (int j = 0; j < 4; ++j) o[i][j] = 0.f;
    }

    for (int kt = 0; kt < SEQ / 64; ++kt) {
        const int k0 = kt * 64;
        // Load K (d-major) and V (k-major) tiles.
        for (int idx = t; idx < 64 * 64; idx += 256) {
            int k = idx >> 6, d = idx & 63;
            Ks[d * QP + k] = kptr[(size_t)(k0 + k) * D_EMB + d];
            Vs[k * 64 + d] = vptr[(size_t)(k0 + k) * D_EMB + d];
        }
        __syncthreads();

        // Scores s = Q·K (scale already folded into Q).
        float s[4][4];
#pragma unroll
        for (int i = 0; i < 4; ++i)
#pragma unroll
            for (int j = 0; j < 4; ++j) s[i][j] = 0.f;

#pragma unroll 8
        for (int d = 0; d < 64; ++d) {
            float a[4], bb[4];
#pragma unroll
            for (int i = 0; i < 4; ++i) a[i]  = Qs[d * QP + ty * 4 + i];
#pragma unroll
            for (int j = 0; j < 4; ++j) bb[j] = Ks[d * QP + tx * 4 + j];
#pragma unroll
            for (int i = 0; i < 4; ++i)
#pragma unroll
                for (int j = 0; j < 4; ++j)
                    s[i][j] = fmaf(a[i], bb[j], s[i][j]);
        }

        // Online softmax per query row (reduce over the 16 tx lanes).
#pragma unroll
        for (int i = 0; i < 4; ++i) {
            float mx = s[i][0];
#pragma unroll
            for (int j = 1; j < 4; ++j) mx = fmaxf(mx, s[i][j]);
#pragma unroll
            for (int off = 1; off < 16; off <<= 1)
                mx = fmaxf(mx, __shfl_xor_sync(0xffffffffu, mx, off));
            float mnew  = fmaxf(mrow[i], mx);
            float alpha = __expf(mrow[i] - mnew);
            mrow[i] = mnew;
            float rs = 0.f;
#pragma unroll
            for (int j = 0; j < 4; ++j) {
                float p = __expf(s[i][j] - mnew);
                s[i][j] = p;
                rs += p;
            }
#pragma unroll
            for (int off = 1; off < 16; off <<= 1)
                rs += __shfl_xor_sync(0xffffffffu, rs, off);
            lrow[i] = lrow[i] * alpha + rs;
#pragma unroll
            for (int j = 0; j < 4; ++j) {
                o[i][j] *= alpha;
                Ps[(ty * 4 + i) * QP + tx * 4 + j] = s[i][j];
            }
        }
        __syncthreads();

        // o += P @ V
#pragma unroll 8
        for (int k = 0; k < 64; ++k) {
            float a[4], bb[4];
#pragma unroll
            for (int i = 0; i < 4; ++i) a[i]  = Ps[(ty * 4 + i) * QP + k];
#pragma unroll
            for (int j = 0; j < 4; ++j) bb[j] = Vs[k * 64 + tx * 4 + j];
#pragma unroll
            for (int i = 0; i < 4; ++i)
#pragma unroll
                for (int j = 0; j < 4; ++j)
                    o[i][j] = fmaf(a[i], bb[j], o[i][j]);
        }
        __syncthreads();
    }

    // Normalize and write: out[b, q, h*64 + d]
#pragma unroll
    for (int i = 0; i < 4; ++i) {
        float inv = 1.f / lrow[i];
        const size_t row = (size_t)(b * SEQ + q0 + ty * 4 + i) * D_EMB + h * DK;
#pragma unroll
        for (int j = 0; j < 4; ++j)
            out[row + tx * 4 + j] = o[i][j] * inv;
    }
}

// ---------------------------------------------------------------------------
extern "C" void kernel_launch(void* const* d_in, const int* in_sizes, int n_in,
                              void* d_out, int out_size)
{
    const float* Q   = (const float*)d_in[0];
    const float* K   = (const float*)d_in[1];
    const float* V   = (const float*)d_in[2];
    const float* W_Q = (const float*)d_in[3];
    const float* b_Q = (const float*)d_in[4];
    const float* W_K = (const float*)d_in[5];
    const float* b_K = (const float*)d_in[6];
    const float* W_V = (const float*)d_in[7];
    const float* b_V = (const float*)d_in[8];
    const float* W_O = (const float*)d_in[9];
    const float* b_O = (const float*)d_in[10];
    float* out = (float*)d_out;

    float* gq; cudaGetSymbolAddress((void**)&gq, g_q);
    float* gk; cudaGetSymbolAddress((void**)&gk, g_k);
    float* gv; cudaGetSymbolAddress((void**)&gv, g_v);
    float* ga; cudaGetSymbolAddress((void**)&ga, g_attn);

    cudaFuncSetAttribute(attn_kernel,
                         cudaFuncAttributeMaxDynamicSharedMemorySize,
                         ATTN_SMEM_BYTES);

    dim3 gblk(256);
    dim3 ggrd(D_EMB / 128, MROWS / 128);   // (8, 32)

    gemm_nt_bias<<<ggrd, gblk>>>(Q, W_Q, b_Q, gq);
    gemm_nt_bias<<<ggrd, gblk>>>(K, W_K, b_K, gk);
    gemm_nt_bias<<<ggrd, gblk>>>(V, W_V, b_V, gv);

    dim3 agrd(SEQ / 64, N_HEADS, BATCH);   // (32, 16, 2)
    attn_kernel<<<agrd, 256, ATTN_SMEM_BYTES>>>(ga);

    gemm_nt_bias<<<ggrd, gblk>>>(ga, W_O, b_O, out);
}

// round 2
// speedup vs baseline: 3.3232x; 3.3232x over previous
#include <cuda_runtime.h>
#include <math.h>
#include <stdint.h>

#define D_EMB   1024
#define N_HEADS 16
#define DK      64
#define BATCH   2
#define SEQ     2048
#define MROWS   (BATCH*SEQ)   // 4096

// Scratch (allocation-free rule: __device__ globals)
__device__ float g_q[MROWS * D_EMB];
__device__ float g_k[MROWS * D_EMB];
__device__ float g_v[MROWS * D_EMB];
__device__ float g_attn[MROWS * D_EMB];

__device__ __forceinline__ float to_tf32(float x) {
    asm("cvt.rna.tf32.f32 %0, %0;" : "+f"(x));
    return x;
}

__device__ __forceinline__ void mma_tf32(float d[4],
                                         uint32_t a0, uint32_t a1, uint32_t a2, uint32_t a3,
                                         uint32_t b0, uint32_t b1)
{
    asm volatile(
        "mma.sync.aligned.m16n8k8.row.col.f32.tf32.tf32.f32 "
        "{%0,%1,%2,%3}, {%4,%5,%6,%7}, {%8,%9}, {%0,%1,%2,%3};\n"
        : "+f"(d[0]), "+f"(d[1]), "+f"(d[2]), "+f"(d[3])
        : "r"(a0), "r"(a1), "r"(a2), "r"(a3), "r"(b0), "r"(b1));
}

// ---------------------------------------------------------------------------
// tf32 GEMM (NT + bias): C[m,n] = sum_k A[m,k]*W[n,k] + bias[n]
// BM=BN=128, BK=32, 256 threads = 8 warps (2x4), warp tile 64x32.
// SMEM: row-major, pitch 36 floats (conflict-free fragment loads).
// ---------------------------------------------------------------------------
#define GP 36

__global__ __launch_bounds__(256, 2)
void gemm_tf32(const float* __restrict__ A,
               const float* __restrict__ W,
               const float* __restrict__ bias,
               float* __restrict__ C)
{
    __shared__ float As[128 * GP];
    __shared__ float Ws[128 * GP];
    const uint32_t* Asu = (const uint32_t*)As;
    const uint32_t* Wsu = (const uint32_t*)Ws;

    const int t    = threadIdx.x;
    const int lane = t & 31;
    const int w    = t >> 5;
    const int wm   = w >> 2;     // 0..1
    const int wn   = w & 3;      // 0..3
    const int m0   = blockIdx.y * 128;
    const int n0   = blockIdx.x * 128;

    // GMEM load mapping: thread covers rows (t>>3)+32i, fixed kq = t&7.
    const int lrow = t >> 3;     // 0..31
    const int kq   = t & 7;      // float4 index within the 32-wide k slab
    const float* Ag = A + (size_t)(m0 + lrow) * D_EMB + kq * 4;
    const float* Wg = W + (size_t)(n0 + lrow) * D_EMB + kq * 4;

    float acc[4][4][4];
#pragma unroll
    for (int i = 0; i < 4; ++i)
#pragma unroll
        for (int j = 0; j < 4; ++j)
#pragma unroll
            for (int q = 0; q < 4; ++q) acc[i][j][q] = 0.f;

    float4 ra[4], rw[4];

    // prologue: slab 0
#pragma unroll
    for (int i = 0; i < 4; ++i) {
        ra[i] = *(const float4*)(Ag + (size_t)i * 32 * D_EMB);
        rw[i] = *(const float4*)(Wg + (size_t)i * 32 * D_EMB);
    }
#pragma unroll
    for (int i = 0; i < 4; ++i) {
        float4 va = ra[i], vw = rw[i];
        float* pa = &As[(lrow + 32 * i) * GP + kq * 4];
        pa[0] = to_tf32(va.x); pa[1] = to_tf32(va.y);
        pa[2] = to_tf32(va.z); pa[3] = to_tf32(va.w);
        float* pw = &Ws[(lrow + 32 * i) * GP + kq * 4];
        pw[0] = to_tf32(vw.x); pw[1] = to_tf32(vw.y);
        pw[2] = to_tf32(vw.z); pw[3] = to_tf32(vw.w);
    }
    __syncthreads();

    for (int kt = 0; kt < D_EMB / 32; ++kt) {
        if (kt < D_EMB / 32 - 1) {
            const float* a = Ag + (kt + 1) * 32;
            const float* wp = Wg + (kt + 1) * 32;
#pragma unroll
            for (int i = 0; i < 4; ++i) {
                ra[i] = *(const float4*)(a + (size_t)i * 32 * D_EMB);
                rw[i] = *(const float4*)(wp + (size_t)i * 32 * D_EMB);
            }
        }

#pragma unroll
        for (int ks = 0; ks < 4; ++ks) {
            const int c = ks * 8 + (lane & 3);
            uint32_t af[4][4];
#pragma unroll
            for (int mt = 0; mt < 4; ++mt) {
                const int r = wm * 64 + mt * 16 + (lane >> 2);
                af[mt][0] = Asu[r * GP + c];
                af[mt][1] = Asu[(r + 8) * GP + c];
                af[mt][2] = Asu[r * GP + c + 4];
                af[mt][3] = Asu[(r + 8) * GP + c + 4];
            }
            uint32_t bf[4][2];
#pragma unroll
            for (int nt = 0; nt < 4; ++nt) {
                const int n = wn * 32 + nt * 8 + (lane >> 2);
                bf[nt][0] = Wsu[n * GP + c];
                bf[nt][1] = Wsu[n * GP + c + 4];
            }
#pragma unroll
            for (int mt = 0; mt < 4; ++mt)
#pragma unroll
                for (int nt = 0; nt < 4; ++nt)
                    mma_tf32(acc[mt][nt], af[mt][0], af[mt][1], af[mt][2], af[mt][3],
                             bf[nt][0], bf[nt][1]);
        }

        if (kt < D_EMB / 32 - 1) {
            __syncthreads();
#pragma unroll
            for (int i = 0; i < 4; ++i) {
                float4 va = ra[i], vw = rw[i];
                float* pa = &As[(lrow + 32 * i) * GP + kq * 4];
                pa[0] = to_tf32(va.x); pa[1] = to_tf32(va.y);
                pa[2] = to_tf32(va.z); pa[3] = to_tf32(va.w);
                float* pw = &Ws[(lrow + 32 * i) * GP + kq * 4];
                pw[0] = to_tf32(vw.x); pw[1] = to_tf32(vw.y);
                pw[2] = to_tf32(vw.z); pw[3] = to_tf32(vw.w);
            }
            __syncthreads();
        }
    }

    // epilogue: bias + store (float2)
#pragma unroll
    for (int mt = 0; mt < 4; ++mt) {
        const int r = m0 + wm * 64 + mt * 16 + (lane >> 2);
#pragma unroll
        for (int nt = 0; nt < 4; ++nt) {
            const int n = n0 + wn * 32 + nt * 8 + (lane & 3) * 2;
            const float b0 = __ldg(&bias[n]);
            const float b1 = __ldg(&bias[n + 1]);
            float2 v0 = make_float2(acc[mt][nt][0] + b0, acc[mt][nt][1] + b1);
            float2 v1 = make_float2(acc[mt][nt][2] + b0, acc[mt][nt][3] + b1);
            *(float2*)&C[(size_t)r * D_EMB + n]       = v0;
            *(float2*)&C[(size_t)(r + 8) * D_EMB + n] = v1;
        }
    }
}

// ---------------------------------------------------------------------------
// Flash attention with tf32 mma.sync.
// Grid (S/64, H, B), 128 threads = 4 warps; each warp owns 16 query rows.
// SMEM (dynamic): Qs[64][68], Ks[64][68], Ps[64][68], Vs[64][72].
// ---------------------------------------------------------------------------
#define AP 68
#define VP 72
#define ATTN_SMEM_BYTES ((3 * 64 * AP + 64 * VP) * 4)

__global__ __launch_bounds__(128)
void attn_tf32(float* __restrict__ out)
{
    extern __shared__ float sm[];
    float* Qs = sm;                 // [q][d] pitch AP
    float* Ks = Qs + 64 * AP;       // [key][d] pitch AP
    float* Ps = Ks + 64 * AP;       // [q][key] pitch AP
    float* Vs = Ps + 64 * AP;       // [key][d] pitch VP
    const uint32_t* Qsu = (const uint32_t*)Qs;
    const uint32_t* Ksu = (const uint32_t*)Ks;
    const uint32_t* Psu = (const uint32_t*)Ps;
    const uint32_t* Vsu = (const uint32_t*)Vs;

    const int t    = threadIdx.x;
    const int lane = t & 31;
    const int warp = t >> 5;
    const int q0   = blockIdx.x * 64;
    const int h    = blockIdx.y;
    const int b    = blockIdx.z;

    const int r  = lane >> 2;            // row within 16-row m-tile (+8 for second)
    const int cg = lane & 3;             // col group
    const int qr = warp * 16 + r;        // local q row (first of pair)

    const float* qptr = g_q + (size_t)(b * SEQ) * D_EMB + h * DK;
    const float* kptr = g_k + (size_t)(b * SEQ) * D_EMB + h * DK;
    const float* vptr = g_v + (size_t)(b * SEQ) * D_EMB + h * DK;

    // Load Q tile, scale folded, tf32-rounded.
    for (int idx = t; idx < 64 * 16; idx += 128) {
        const int row = idx >> 4, f4 = idx & 15;
        float4 v = *(const float4*)&qptr[(size_t)(q0 + row) * D_EMB + f4 * 4];
        float* p = &Qs[row * AP + f4 * 4];
        p[0] = to_tf32(v.x * 0.125f); p[1] = to_tf32(v.y * 0.125f);
        p[2] = to_tf32(v.z * 0.125f); p[3] = to_tf32(v.w * 0.125f);
    }

    float m_[2] = {-INFINITY, -INFINITY};
    float l_[2] = {0.f, 0.f};
    float o[8][4];
#pragma unroll
    for (int nt = 0; nt < 8; ++nt)
#pragma unroll
        for (int q = 0; q < 4; ++q) o[nt][q] = 0.f;

    for (int kt = 0; kt < SEQ / 64; ++kt) {
        const int kbase = kt * 64;
        for (int idx = t; idx < 64 * 16; idx += 128) {
            const int row = idx >> 4, f4 = idx & 15;
            float4 kv = *(const float4*)&kptr[(size_t)(kbase + row) * D_EMB + f4 * 4];
            float4 vv = *(const float4*)&vptr[(size_t)(kbase + row) * D_EMB + f4 * 4];
            float* pk = &Ks[row * AP + f4 * 4];
            pk[0] = to_tf32(kv.x); pk[1] = to_tf32(kv.y);
            pk[2] = to_tf32(kv.z); pk[3] = to_tf32(kv.w);
            float* pv = &Vs[row * VP + f4 * 4];
            pv[0] = to_tf32(vv.x); pv[1] = to_tf32(vv.y);
            pv[2] = to_tf32(vv.z); pv[3] = to_tf32(vv.w);
        }
        __syncthreads();

        // S = Q * K^T  (16 q rows per warp x 64 keys)
        float s[8][4];
#pragma unroll
        for (int nt = 0; nt < 8; ++nt)
#pragma unroll
            for (int q = 0; q < 4; ++q) s[nt][q] = 0.f;

#pragma unroll
        for (int ks = 0; ks < 8; ++ks) {
            const int c = ks * 8 + cg;
            const uint32_t a0 = Qsu[qr * AP + c];
            const uint32_t a1 = Qsu[(qr + 8) * AP + c];
            const uint32_t a2 = Qsu[qr * AP + c + 4];
            const uint32_t a3 = Qsu[(qr + 8) * AP + c + 4];
#pragma unroll
            for (int nt = 0; nt < 8; ++nt) {
                const int n = nt * 8 + (lane >> 2);
                mma_tf32(s[nt], a0, a1, a2, a3,
                         Ksu[n * AP + c], Ksu[n * AP + c + 4]);
            }
        }

        // online softmax (rows qr and qr+8; reduce across 4 lanes sharing a row)
#pragma unroll
        for (int hlf = 0; hlf < 2; ++hlf) {
            float mx = -INFINITY;
#pragma unroll
            for (int nt = 0; nt < 8; ++nt)
                mx = fmaxf(mx, fmaxf(s[nt][2 * hlf], s[nt][2 * hlf + 1]));
            mx = fmaxf(mx, __shfl_xor_sync(0xffffffffu, mx, 1));
            mx = fmaxf(mx, __shfl_xor_sync(0xffffffffu, mx, 2));
            const float mnew  = fmaxf(m_[hlf], mx);
            const float alpha = __expf(m_[hlf] - mnew);
            m_[hlf] = mnew;
            float rs = 0.f;
#pragma unroll
            for (int nt = 0; nt < 8; ++nt) {
                float p0 = __expf(s[nt][2 * hlf]     - mnew);
                float p1 = __expf(s[nt][2 * hlf + 1] - mnew);
                s[nt][2 * hlf] = p0; s[nt][2 * hlf + 1] = p1;
                rs += p0 + p1;
            }
            rs += __shfl_xor_sync(0xffffffffu, rs, 1);
            rs += __shfl_xor_sync(0xffffffffu, rs, 2);
            l_[hlf] = l_[hlf] * alpha + rs;
#pragma unroll
            for (int nt = 0; nt < 8; ++nt) {
                o[nt][2 * hlf]     *= alpha;
                o[nt][2 * hlf + 1] *= alpha;
            }
        }

        // write P to SMEM in C-layout (tf32-rounded), reload as A-fragments
#pragma unroll
        for (int nt = 0; nt < 8; ++nt) {
            const int col = nt * 8 + cg * 2;
            *(float2*)&Ps[qr * AP + col] =
                make_float2(to_tf32(s[nt][0]), to_tf32(s[nt][1]));
            *(float2*)&Ps[(qr + 8) * AP + col] =
                make_float2(to_tf32(s[nt][2]), to_tf32(s[nt][3]));
        }
        __syncwarp();

        // O += P * V
#pragma unroll
        for (int ks = 0; ks < 8; ++ks) {
            const int c = ks * 8 + cg;   // key index
            const uint32_t a0 = Psu[qr * AP + c];
            const uint32_t a1 = Psu[(qr + 8) * AP + c];
            const uint32_t a2 = Psu[qr * AP + c + 4];
            const uint32_t a3 = Psu[(qr + 8) * AP + c + 4];
#pragma unroll
            for (int nt = 0; nt < 8; ++nt) {
                const int n = nt * 8 + (lane >> 2);
                mma_tf32(o[nt], a0, a1, a2, a3,
                         Vsu[c * VP + n], Vsu[(c + 4) * VP + n]);
            }
        }
        __syncthreads();
    }

    const float inv0 = 1.f / l_[0];
    const float inv1 = 1.f / l_[1];
    const size_t row0 = (size_t)(b * SEQ + q0 + qr) * D_EMB + h * DK;
    const size_t row1 = row0 + 8 * D_EMB;
#pragma unroll
    for (int nt = 0; nt < 8; ++nt) {
        const int col = nt * 8 + cg * 2;
        *(float2*)&out[row0 + col] = make_float2(o[nt][0] * inv0, o[nt][1] * inv0);
        *(float2*)&out[row1 + col] = make_float2(o[nt][2] * inv1, o[nt][3] * inv1);
    }
}

// ---------------------------------------------------------------------------
extern "C" void kernel_launch(void* const* d_in, const int* in_sizes, int n_in,
                              void* d_out, int out_size)
{
    const float* Q   = (const float*)d_in[0];
    const float* K   = (const float*)d_in[1];
    const float* V   = (const float*)d_in[2];
    const float* W_Q = (const float*)d_in[3];
    const float* b_Q = (const float*)d_in[4];
    const float* W_K = (const float*)d_in[5];
    const float* b_K = (const float*)d_in[6];
    const float* W_V = (const float*)d_in[7];
    const float* b_V = (const float*)d_in[8];
    const float* W_O = (const float*)d_in[9];
    const float* b_O = (const float*)d_in[10];
    float* out = (float*)d_out;

    float* gq; cudaGetSymbolAddress((void**)&gq, g_q);
    float* gk; cudaGetSymbolAddress((void**)&gk, g_k);
    float* gv; cudaGetSymbolAddress((void**)&gv, g_v);
    float* ga; cudaGetSymbolAddress((void**)&ga, g_attn);

    cudaFuncSetAttribute(attn_tf32,
                         cudaFuncAttributeMaxDynamicSharedMemorySize,
                         ATTN_SMEM_BYTES);

    dim3 gblk(256);
    dim3 ggrd(D_EMB / 128, MROWS / 128);   // (8, 32)

    gemm_tf32<<<ggrd, gblk>>>(Q, W_Q, b_Q, gq);
    gemm_tf32<<<ggrd, gblk>>>(K, W_K, b_K, gk);
    gemm_tf32<<<ggrd, gblk>>>(V, W_V, b_V, gv);

    dim3 agrd(SEQ / 64, N_HEADS, BATCH);   // (32, 16, 2)
    attn_tf32<<<agrd, 128, ATTN_SMEM_BYTES>>>(ga);

    gemm_tf32<<<ggrd, gblk>>>(ga, W_O, b_O, out);
}

// round 3
// speedup vs baseline: 3.8687x; 1.1641x over previous
#include <cuda_runtime.h>
#include <math.h>
#include <stdint.h>

#define D_EMB   1024
#define N_HEADS 16
#define DK      64
#define BATCH   2
#define SEQ     2048
#define MROWS   (BATCH*SEQ)   // 4096

// Scratch (allocation-free rule: __device__ globals)
__device__ float g_q[MROWS * D_EMB];
__device__ float g_k[MROWS * D_EMB];
__device__ float g_v[MROWS * D_EMB];
__device__ float g_attn[MROWS * D_EMB];

__device__ __forceinline__ float to_tf32(float x) {
    asm("cvt.rna.tf32.f32 %0, %0;" : "+f"(x));
    return x;
}

__device__ __forceinline__ void mma_tf32(float d[4],
                                         uint32_t a0, uint32_t a1, uint32_t a2, uint32_t a3,
                                         uint32_t b0, uint32_t b1)
{
    asm volatile(
        "mma.sync.aligned.m16n8k8.row.col.f32.tf32.tf32.f32 "
        "{%0,%1,%2,%3}, {%4,%5,%6,%7}, {%8,%9}, {%0,%1,%2,%3};\n"
        : "+f"(d[0]), "+f"(d[1]), "+f"(d[2]), "+f"(d[3])
        : "r"(a0), "r"(a1), "r"(a2), "r"(a3), "r"(b0), "r"(b1));
}

// ---------------------------------------------------------------------------
// tf32 GEMM (NT + bias): C[m,n] = sum_k A[m,k]*W[n,k] + bias[n]
// BM=BN=128, BK=32, 256 threads = 8 warps (2x4), warp tile 64x32.
// ---------------------------------------------------------------------------
#define GP 36

__global__ __launch_bounds__(256, 2)
void gemm_tf32(const float* __restrict__ A,
               const float* __restrict__ W,
               const float* __restrict__ bias,
               float* __restrict__ C)
{
    __shared__ float As[128 * GP];
    __shared__ float Ws[128 * GP];
    const uint32_t* Asu = (const uint32_t*)As;
    const uint32_t* Wsu = (const uint32_t*)Ws;

    const int t    = threadIdx.x;
    const int lane = t & 31;
    const int w    = t >> 5;
    const int wm   = w >> 2;     // 0..1
    const int wn   = w & 3;      // 0..3
    const int m0   = blockIdx.y * 128;
    const int n0   = blockIdx.x * 128;

    const int lrow = t >> 3;     // 0..31
    const int kq   = t & 7;      // float4 index within the 32-wide k slab
    const float* Ag = A + (size_t)(m0 + lrow) * D_EMB + kq * 4;
    const float* Wg = W + (size_t)(n0 + lrow) * D_EMB + kq * 4;

    float acc[4][4][4];
#pragma unroll
    for (int i = 0; i < 4; ++i)
#pragma unroll
        for (int j = 0; j < 4; ++j)
#pragma unroll
            for (int q = 0; q < 4; ++q) acc[i][j][q] = 0.f;

    float4 ra[4], rw[4];

#pragma unroll
    for (int i = 0; i < 4; ++i) {
        ra[i] = *(const float4*)(Ag + (size_t)i * 32 * D_EMB);
        rw[i] = *(const float4*)(Wg + (size_t)i * 32 * D_EMB);
    }
#pragma unroll
    for (int i = 0; i < 4; ++i) {
        float4 va = ra[i], vw = rw[i];
        float* pa = &As[(lrow + 32 * i) * GP + kq * 4];
        pa[0] = to_tf32(va.x); pa[1] = to_tf32(va.y);
        pa[2] = to_tf32(va.z); pa[3] = to_tf32(va.w);
        float* pw = &Ws[(lrow + 32 * i) * GP + kq * 4];
        pw[0] = to_tf32(vw.x); pw[1] = to_tf32(vw.y);
        pw[2] = to_tf32(vw.z); pw[3] = to_tf32(vw.w);
    }
    __syncthreads();

    for (int kt = 0; kt < D_EMB / 32; ++kt) {
        if (kt < D_EMB / 32 - 1) {
            const float* a  = Ag + (kt + 1) * 32;
            const float* wp = Wg + (kt + 1) * 32;
#pragma unroll
            for (int i = 0; i < 4; ++i) {
                ra[i] = *(const float4*)(a + (size_t)i * 32 * D_EMB);
                rw[i] = *(const float4*)(wp + (size_t)i * 32 * D_EMB);
            }
        }

#pragma unroll
        for (int ks = 0; ks < 4; ++ks) {
            const int c = ks * 8 + (lane & 3);
            uint32_t af[4][4];
#pragma unroll
            for (int mt = 0; mt < 4; ++mt) {
                const int r = wm * 64 + mt * 16 + (lane >> 2);
                af[mt][0] = Asu[r * GP + c];
                af[mt][1] = Asu[(r + 8) * GP + c];
                af[mt][2] = Asu[r * GP + c + 4];
                af[mt][3] = Asu[(r + 8) * GP + c + 4];
            }
            uint32_t bf[4][2];
#pragma unroll
            for (int nt = 0; nt < 4; ++nt) {
                const int n = wn * 32 + nt * 8 + (lane >> 2);
                bf[nt][0] = Wsu[n * GP + c];
                bf[nt][1] = Wsu[n * GP + c + 4];
            }
#pragma unroll
            for (int mt = 0; mt < 4; ++mt)
#pragma unroll
                for (int nt = 0; nt < 4; ++nt)
                    mma_tf32(acc[mt][nt], af[mt][0], af[mt][1], af[mt][2], af[mt][3],
                             bf[nt][0], bf[nt][1]);
        }

        if (kt < D_EMB / 32 - 1) {
            __syncthreads();
#pragma unroll
            for (int i = 0; i < 4; ++i) {
                float4 va = ra[i], vw = rw[i];
                float* pa = &As[(lrow + 32 * i) * GP + kq * 4];
                pa[0] = to_tf32(va.x); pa[1] = to_tf32(va.y);
                pa[2] = to_tf32(va.z); pa[3] = to_tf32(va.w);
                float* pw = &Ws[(lrow + 32 * i) * GP + kq * 4];
                pw[0] = to_tf32(vw.x); pw[1] = to_tf32(vw.y);
                pw[2] = to_tf32(vw.z); pw[3] = to_tf32(vw.w);
            }
            __syncthreads();
        }
    }

#pragma unroll
    for (int mt = 0; mt < 4; ++mt) {
        const int r = m0 + wm * 64 + mt * 16 + (lane >> 2);
#pragma unroll
        for (int nt = 0; nt < 4; ++nt) {
            const int n = n0 + wn * 32 + nt * 8 + (lane & 3) * 2;
            const float b0 = __ldg(&bias[n]);
            const float b1 = __ldg(&bias[n + 1]);
            float2 v0 = make_float2(acc[mt][nt][0] + b0, acc[mt][nt][1] + b1);
            float2 v1 = make_float2(acc[mt][nt][2] + b0, acc[mt][nt][3] + b1);
            *(float2*)&C[(size_t)r * D_EMB + n]       = v0;
            *(float2*)&C[(size_t)(r + 8) * D_EMB + n] = v1;
        }
    }
}

// ---------------------------------------------------------------------------
// Flash attention, tf32 mma, P kept in registers (C-frag -> A-frag reuse with
// key-permutation absorbed into V row indexing).
// Grid (S/128, H, B), 128 threads = 4 warps; each warp owns 32 query rows.
// SMEM: Qs[128][68], Ks[64][68], Vs[64][68].
// ---------------------------------------------------------------------------
#define AP 68
#define ATTN_SMEM_BYTES ((128 * AP + 64 * AP + 64 * AP) * 4)

__global__ __launch_bounds__(128)
void attn_tf32(float* __restrict__ out)
{
    extern __shared__ float sm[];
    float* Qs = sm;                  // [q][d]   pitch AP (128 rows)
    float* Ks = Qs + 128 * AP;       // [key][d] pitch AP (64 rows)
    float* Vs = Ks + 64 * AP;        // [key][d] pitch AP (64 rows)
    const uint32_t* Qsu = (const uint32_t*)Qs;
    const uint32_t* Ksu = (const uint32_t*)Ks;
    const uint32_t* Vsu = (const uint32_t*)Vs;

    const int t    = threadIdx.x;
    const int lane = t & 31;
    const int warp = t >> 5;
    const int r    = lane >> 2;          // 0..7
    const int cg   = lane & 3;           // 0..3
    const int q0   = blockIdx.x * 128;
    const int h    = blockIdx.y;
    const int b    = blockIdx.z;

    const float* qptr = g_q + (size_t)(b * SEQ) * D_EMB + h * DK;
    const float* kptr = g_k + (size_t)(b * SEQ) * D_EMB + h * DK;
    const float* vptr = g_v + (size_t)(b * SEQ) * D_EMB + h * DK;

    // Load Q tile (128 rows), scale folded, tf32-rounded.
    for (int idx = t; idx < 128 * 16; idx += 128) {
        const int row = idx >> 4, f4 = idx & 15;
        float4 v = *(const float4*)&qptr[(size_t)(q0 + row) * D_EMB + f4 * 4];
        float* p = &Qs[row * AP + f4 * 4];
        p[0] = to_tf32(v.x * 0.125f); p[1] = to_tf32(v.y * 0.125f);
        p[2] = to_tf32(v.z * 0.125f); p[3] = to_tf32(v.w * 0.125f);
    }

    float m_[2][2], l_[2][2];
    float o[2][8][4];
#pragma unroll
    for (int mt = 0; mt < 2; ++mt) {
        m_[mt][0] = m_[mt][1] = -INFINITY;
        l_[mt][0] = l_[mt][1] = 0.f;
#pragma unroll
        for (int nt = 0; nt < 8; ++nt)
#pragma unroll
            for (int q = 0; q < 4; ++q) o[mt][nt][q] = 0.f;
    }

    for (int kt = 0; kt < SEQ / 64; ++kt) {
        const int kbase = kt * 64;
        // Load K and V tiles (64 rows each).
        for (int idx = t; idx < 64 * 16; idx += 128) {
            const int row = idx >> 4, f4 = idx & 15;
            float4 kv = *(const float4*)&kptr[(size_t)(kbase + row) * D_EMB + f4 * 4];
            float4 vv = *(const float4*)&vptr[(size_t)(kbase + row) * D_EMB + f4 * 4];
            float* pk = &Ks[row * AP + f4 * 4];
            pk[0] = to_tf32(kv.x); pk[1] = to_tf32(kv.y);
            pk[2] = to_tf32(kv.z); pk[3] = to_tf32(kv.w);
            float* pv = &Vs[row * AP + f4 * 4];
            pv[0] = to_tf32(vv.x); pv[1] = to_tf32(vv.y);
            pv[2] = to_tf32(vv.z); pv[3] = to_tf32(vv.w);
        }
        __syncthreads();

        // S = Q * K^T  (32 q rows per warp x 64 keys)
        float s[2][8][4];
#pragma unroll
        for (int mt = 0; mt < 2; ++mt)
#pragma unroll
            for (int nt = 0; nt < 8; ++nt)
#pragma unroll
                for (int q = 0; q < 4; ++q) s[mt][nt][q] = 0.f;

#pragma unroll
        for (int ks = 0; ks < 8; ++ks) {
            const int c = ks * 8 + cg;
#pragma unroll
            for (int mt = 0; mt < 2; ++mt) {
                const int qr = warp * 32 + mt * 16 + r;
                const uint32_t a0 = Qsu[qr * AP + c];
                const uint32_t a1 = Qsu[(qr + 8) * AP + c];
                const uint32_t a2 = Qsu[qr * AP + c + 4];
                const uint32_t a3 = Qsu[(qr + 8) * AP + c + 4];
#pragma unroll
                for (int nt = 0; nt < 8; ++nt) {
                    const int n = nt * 8 + r;
                    mma_tf32(s[mt][nt], a0, a1, a2, a3,
                             Ksu[n * AP + c], Ksu[n * AP + c + 4]);
                }
            }
        }

        // Online softmax. C-frag rows: hlf 0 -> row r, hlf 1 -> row r+8.
        // Lanes sharing a row differ only in cg -> shuffle xor 1, 2.
#pragma unroll
        for (int mt = 0; mt < 2; ++mt) {
#pragma unroll
            for (int hlf = 0; hlf < 2; ++hlf) {
                float mx = -INFINITY;
#pragma unroll
                for (int nt = 0; nt < 8; ++nt)
                    mx = fmaxf(mx, fmaxf(s[mt][nt][2 * hlf], s[mt][nt][2 * hlf + 1]));
                mx = fmaxf(mx, __shfl_xor_sync(0xffffffffu, mx, 1));
                mx = fmaxf(mx, __shfl_xor_sync(0xffffffffu, mx, 2));
                const float mnew  = fmaxf(m_[mt][hlf], mx);
                const float alpha = __expf(m_[mt][hlf] - mnew);
                m_[mt][hlf] = mnew;
                float rs = 0.f;
#pragma unroll
                for (int nt = 0; nt < 8; ++nt) {
                    float p0 = __expf(s[mt][nt][2 * hlf]     - mnew);
                    float p1 = __expf(s[mt][nt][2 * hlf + 1] - mnew);
                    rs += p0 + p1;
                    s[mt][nt][2 * hlf]     = to_tf32(p0);
                    s[mt][nt][2 * hlf + 1] = to_tf32(p1);
                }
                rs += __shfl_xor_sync(0xffffffffu, rs, 1);
                rs += __shfl_xor_sync(0xffffffffu, rs, 2);
                l_[mt][hlf] = l_[mt][hlf] * alpha + rs;
#pragma unroll
                for (int nt = 0; nt < 8; ++nt) {
                    o[mt][nt][2 * hlf]     *= alpha;
                    o[mt][nt][2 * hlf + 1] *= alpha;
                }
            }
        }

        // O += P * V with P straight from registers.
        // C-frag (row r/r+8, cols 2cg,2cg+1) reused as A-frag (m16k8) under the
        // within-8 key permutation pi: a0<-d0, a1<-d2, a2<-d1, a3<-d3; the
        // permutation is undone by reading V rows ks*8+2cg and ks*8+2cg+1.
#pragma unroll
        for (int ks = 0; ks < 8; ++ks) {
            const int v0row = ks * 8 + 2 * cg;
#pragma unroll
            for (int mt = 0; mt < 2; ++mt) {
                const uint32_t a0 = __float_as_uint(s[mt][ks][0]);
                const uint32_t a1 = __float_as_uint(s[mt][ks][2]);
                const uint32_t a2 = __float_as_uint(s[mt][ks][1]);
                const uint32_t a3 = __float_as_uint(s[mt][ks][3]);
#pragma unroll
                for (int nt = 0; nt < 8; ++nt) {
                    const int n = nt * 8 + r;
                    mma_tf32(o[mt][nt], a0, a1, a2, a3,
                             Vsu[v0row * AP + n], Vsu[(v0row + 1) * AP + n]);
                }
            }
        }
        __syncthreads();
    }

    // Normalize and write out[b, q, h*64 + d].
#pragma unroll
    for (int mt = 0; mt < 2; ++mt) {
        const float inv0 = 1.f / l_[mt][0];
        const float inv1 = 1.f / l_[mt][1];
        const size_t row0 = (size_t)(b * SEQ + q0 + warp * 32 + mt * 16 + r) * D_EMB + h * DK;
        const size_t row1 = row0 + 8 * D_EMB;
#pragma unroll
        for (int nt = 0; nt < 8; ++nt) {
            const int col = nt * 8 + cg * 2;
            *(float2*)&out[row0 + col] = make_float2(o[mt][nt][0] * inv0, o[mt][nt][1] * inv0);
            *(float2*)&out[row1 + col] = make_float2(o[mt][nt][2] * inv1, o[mt][nt][3] * inv1);
        }
    }
}

// ---------------------------------------------------------------------------
extern "C" void kernel_launch(void* const* d_in, const int* in_sizes, int n_in,
                              void* d_out, int out_size)
{
    const float* Q   = (const float*)d_in[0];
    const float* K   = (const float*)d_in[1];
    const float* V   = (const float*)d_in[2];
    const float* W_Q = (const float*)d_in[3];
    const float* b_Q = (const float*)d_in[4];
    const float* W_K = (const float*)d_in[5];
    const float* b_K = (const float*)d_in[6];
    const float* W_V = (const float*)d_in[7];
    const float* b_V = (const float*)d_in[8];
    const float* W_O = (const float*)d_in[9];
    const float* b_O = (const float*)d_in[10];
    float* out = (float*)d_out;

    float* gq; cudaGetSymbolAddress((void**)&gq, g_q);
    float* gk; cudaGetSymbolAddress((void**)&gk, g_k);
    float* gv; cudaGetSymbolAddress((void**)&gv, g_v);
    float* ga; cudaGetSymbolAddress((void**)&ga, g_attn);

    cudaFuncSetAttribute(attn_tf32,
                         cudaFuncAttributeMaxDynamicSharedMemorySize,
                         ATTN_SMEM_BYTES);

    dim3 gblk(256);
    dim3 ggrd(D_EMB / 128, MROWS / 128);   // (8, 32)

    gemm_tf32<<<ggrd, gblk>>>(Q, W_Q, b_Q, gq);
    gemm_tf32<<<ggrd, gblk>>>(K, W_K, b_K, gk);
    gemm_tf32<<<ggrd, gblk>>>(V, W_V, b_V, gv);

    dim3 agrd(SEQ / 128, N_HEADS, BATCH);  // (16, 16, 2)
    attn_tf32<<<agrd, 128, ATTN_SMEM_BYTES>>>(ga);

    gemm_tf32<<<ggrd, gblk>>>(ga, W_O, b_O, out);
}